// round 13
// baseline (speedup 1.0000x reference)
#include <cuda_runtime.h>
#include <cuda_bf16.h>

#define N_NODES 50000
#define IN_CH   64
#define REL_DIM 32
#define N_EDGES 800000
#define NEG_SLOPE 0.01f

#define NBLK   740            // 5 blocks/SM x 148 SMs — all co-resident
#define NTHR   256
#define GT     (NBLK * NTHR)
#define GWARPS (NBLK * 8)
#define NCHUNK ((N_NODES + 255) / 256)   // 196
#define NBAR   9

// ---------------- scratch ----------------
__device__ float    g_ew1  [N_EDGES];
__device__ float    g_ew2  [N_EDGES];
__device__ float    g_alpha[N_EDGES];
__device__ float    g_x    [N_NODES * IN_CH];   // layer-1 transformed feats
__device__ float    g_x2   [N_NODES * IN_CH];   // layer-2 transformed feats
__device__ float    g_h    [N_NODES * IN_CH];   // layer-1 output
__device__ float    g_ai   [N_NODES];
__device__ float    g_aj   [N_NODES];
__device__ unsigned g_mkey1[N_NODES];
__device__ float    g_ssum1[N_NODES];
__device__ unsigned g_mkey2[N_NODES];
__device__ float    g_ssum2[N_NODES];
__device__ int      g_deg  [N_NODES];
__device__ int      g_rowst[N_NODES];
__device__ int      g_curs [N_NODES];
__device__ int      g_bsum [NCHUNK];
__device__ int      g_boff [NCHUNK];
__device__ int2     g_edge [N_EDGES];          // {src, eid} in dst-CSR order
__device__ float    g_v1   [REL_DIM];
__device__ float    g_v2   [REL_DIM];
__device__ float    g_ewc  [2];
__device__ unsigned gA[NBAR];
__device__ unsigned gD[NBAR];

struct SmemXF { float Wt[IN_CH * IN_CH]; float bsh[IN_CH], ais[IN_CH], ajs[IN_CH]; };
// Wse[k*32+l] = relW[2l][k] (even out-channels), Wso = odd out-channels; conflict-free
struct SmemGT { float Wse[REL_DIM * 32]; float Wso[REL_DIM * 32]; float Bs[IN_CH]; };
struct SmemEW { float sv1[REL_DIM], sv2[REL_DIM], sc[2]; };
struct SmemSC { int wsum[8]; };
union Smem { SmemXF xf; SmemGT gt; SmemEW ew; SmemSC sc; };

__device__ __forceinline__ unsigned fkey(float f) {
    unsigned b = __float_as_uint(f);
    return (b & 0x80000000u) ? ~b : (b | 0x80000000u);
}
__device__ __forceinline__ float funkey(unsigned u) {
    unsigned b = (u & 0x80000000u) ? (u & 0x7fffffffu) : ~u;
    return __uint_as_float(b);
}

// ---- software grid barrier (arrive/depart, self-resetting for replay) ----------
__device__ __forceinline__ void gsync(int id) {
    __syncthreads();
    if (threadIdx.x == 0) {
        __threadfence();
        atomicAdd(&gA[id], 1u);
        while (*((volatile unsigned*)&gA[id]) < (unsigned)NBLK) __nanosleep(64);
        unsigned d = atomicAdd(&gD[id], 1u);
        if (d == (unsigned)(NBLK - 1)) {
            *((volatile unsigned*)&gA[id]) = 0u;
            *((volatile unsigned*)&gD[id]) = 0u;
        }
        __threadfence();
    }
    __syncthreads();
}

// ---- node transform, 4 nodes per warp iteration (amortized smem weight reads) ---
__device__ void do_transform(Smem* sm, const float* __restrict__ in,
                             float* __restrict__ xout,
                             const float* __restrict__ W, const float* __restrict__ b,
                             const float* __restrict__ aiw, const float* __restrict__ aib,
                             const float* __restrict__ ajw, const float* __restrict__ ajb,
                             int gwarp, int lane)
{
    int tid = threadIdx.x;
    __syncthreads();          // protect smem union vs previous phase
    for (int i = tid; i < IN_CH * IN_CH; i += NTHR) {
        int c = i >> 6, k = i & 63;
        sm->xf.Wt[k * IN_CH + c] = W[i];
    }
    if (tid < IN_CH) { sm->xf.bsh[tid] = b[tid]; sm->xf.ais[tid] = aiw[tid]; sm->xf.ajs[tid] = ajw[tid]; }
    float aib0 = aib[0], ajb0 = ajb[0];
    __syncthreads();

    for (int n0 = gwarp * 4; n0 < N_NODES; n0 += GWARPS * 4) {
        float iv0[4], iv1[4], acc0[4], acc1[4];
#pragma unroll
        for (int i = 0; i < 4; i++) {
            int n = n0 + i;
            bool ok = (n < N_NODES);
            iv0[i] = ok ? in[(size_t)n * IN_CH + lane] : 0.f;
            iv1[i] = ok ? in[(size_t)n * IN_CH + 32 + lane] : 0.f;
            acc0[i] = sm->xf.bsh[lane];
            acc1[i] = sm->xf.bsh[32 + lane];
        }
#pragma unroll 8
        for (int k = 0; k < 32; k++) {
            float w0 = sm->xf.Wt[k * IN_CH + lane];
            float w1 = sm->xf.Wt[k * IN_CH + 32 + lane];
#pragma unroll
            for (int i = 0; i < 4; i++) {
                float v = __shfl_sync(0xffffffffu, iv0[i], k);
                acc0[i] += v * w0;
                acc1[i] += v * w1;
            }
        }
#pragma unroll 8
        for (int k = 0; k < 32; k++) {
            float w0 = sm->xf.Wt[(k + 32) * IN_CH + lane];
            float w1 = sm->xf.Wt[(k + 32) * IN_CH + 32 + lane];
#pragma unroll
            for (int i = 0; i < 4; i++) {
                float v = __shfl_sync(0xffffffffu, iv1[i], k);
                acc0[i] += v * w0;
                acc1[i] += v * w1;
            }
        }
#pragma unroll
        for (int i = 0; i < 4; i++) {
            int n = n0 + i;
            if (n < N_NODES) {
                xout[(size_t)n * IN_CH + lane]      = acc0[i];
                xout[(size_t)n * IN_CH + 32 + lane] = acc1[i];
                float ap = acc0[i] * sm->xf.ais[lane] + acc1[i] * sm->xf.ais[32 + lane];
                float jp = acc0[i] * sm->xf.ajs[lane] + acc1[i] * sm->xf.ajs[32 + lane];
#pragma unroll
                for (int o = 16; o > 0; o >>= 1) {
                    ap += __shfl_xor_sync(0xffffffffu, ap, o);
                    jp += __shfl_xor_sync(0xffffffffu, jp, o);
                }
                if (lane == 0) { g_ai[n] = ap + aib0; g_aj[n] = jp + ajb0; }
            }
        }
    }
}

// ---- alpha + segment max over src ----------------------------------------------
__device__ void do_alpha_max(const int* __restrict__ src, const int* __restrict__ dst,
                             const float* __restrict__ ew, unsigned* __restrict__ mkey, int gtid)
{
    for (int i = gtid; i < N_EDGES; i += GT) {
        int s = src[i], d = dst[i];
        float a = g_ai[d] + g_aj[s] + ew[i];
        a = a > 0.0f ? a : NEG_SLOPE * a;
        g_alpha[i] = a;
        atomicMax(&mkey[s], fkey(a));
    }
}

// ---- ex = exp(alpha - m[src]); segment sum over src ----------------------------
__device__ void do_exp_sum(const int* __restrict__ src,
                           const unsigned* __restrict__ mkey, float* __restrict__ ssum, int gtid)
{
    for (int i = gtid; i < N_EDGES; i += GT) {
        int s = src[i];
        float m = funkey(mkey[s]);
        float ex = __expf(g_alpha[i] - m);
        g_alpha[i] = ex;
        atomicAdd(&ssum[s], ex);
    }
}

// ---- gather + fused rel-projection, 4 nodes per warp group ----------------------
__device__ void do_gatherproj(Smem* sm, const float* __restrict__ x,
                              const float* __restrict__ r,
                              const float* __restrict__ relW,   // [64,32]
                              const float* __restrict__ relB,
                              const float* __restrict__ ssum, float* __restrict__ out,
                              int gwarp, int lane)
{
    int tid = threadIdx.x;
    __syncthreads();          // protect smem union vs previous phase
    for (int i = tid; i < IN_CH * REL_DIM; i += NTHR) {
        int c = i >> 5, k = i & 31;               // relW[c][k]
        if (c & 1) sm->gt.Wso[k * 32 + (c >> 1)] = relW[i];
        else       sm->gt.Wse[k * 32 + (c >> 1)] = relW[i];
    }
    if (tid < IN_CH) sm->gt.Bs[tid] = relB[tid];
    __syncthreads();
    const float2* Bs2 = reinterpret_cast<const float2*>(sm->gt.Bs);

    for (int n0 = gwarp * 4; n0 < N_NODES; n0 += GWARPS * 4) {
        float accx[4], accy[4], accr[4], csum[4];
#pragma unroll
        for (int i = 0; i < 4; i++) { accx[i] = 0.f; accy[i] = 0.f; accr[i] = 0.f; csum[i] = 0.f; }

#pragma unroll
        for (int i = 0; i < 4; i++) {
            int node = n0 + i;
            if (node < N_NODES) {
                int start = g_rowst[node];
                int deg   = g_deg[node];
                int base = 0;
                for (; base + 32 <= deg; base += 32) {
                    int2 se = g_edge[start + base + lane];
                    float cf = __fdividef(g_alpha[se.y], ssum[se.x] + 1e-16f);
                    csum[i] += cf;
#pragma unroll 8
                    for (int j = 0; j < 32; j++) {
                        float cj = __shfl_sync(0xffffffffu, cf,   j);
                        int   sj = __shfl_sync(0xffffffffu, se.x, j);
                        int   ej = __shfl_sync(0xffffffffu, se.y, j);
                        float2 xv = *reinterpret_cast<const float2*>(x + (size_t)sj * IN_CH + 2 * lane);
                        accx[i] += cj * xv.x;
                        accy[i] += cj * xv.y;
                        accr[i] += cj * r[(size_t)ej * REL_DIM + lane];
                    }
                }
                int m = deg - base;
                if (m > 0) {
                    int2 se = make_int2(0, 0);
                    float cf = 0.f;
                    if (lane < m) {
                        se = g_edge[start + base + lane];
                        cf = __fdividef(g_alpha[se.y], ssum[se.x] + 1e-16f);
                    }
                    csum[i] += cf;
#pragma unroll 8
                    for (int j = 0; j < 32; j++) {
                        if (j < m) {
                            float cj = __shfl_sync(0xffffffffu, cf,   j);
                            int   sj = __shfl_sync(0xffffffffu, se.x, j);
                            int   ej = __shfl_sync(0xffffffffu, se.y, j);
                            float2 xv = *reinterpret_cast<const float2*>(x + (size_t)sj * IN_CH + 2 * lane);
                            accx[i] += cj * xv.x;
                            accy[i] += cj * xv.y;
                            accr[i] += cj * r[(size_t)ej * REL_DIM + lane];
                        }
                    }
                }
#pragma unroll
                for (int o = 16; o > 0; o >>= 1)
                    csum[i] += __shfl_xor_sync(0xffffffffu, csum[i], o);
            }
        }

        // fused projection: acc += (accr @ relW^T) for channels (2*lane, 2*lane+1)
#pragma unroll 8
        for (int k = 0; k < REL_DIM; k++) {
            float we = sm->gt.Wse[k * 32 + lane];
            float wo = sm->gt.Wso[k * 32 + lane];
#pragma unroll
            for (int i = 0; i < 4; i++) {
                float v = __shfl_sync(0xffffffffu, accr[i], k);
                accx[i] += v * we;
                accy[i] += v * wo;
            }
        }

        float2 bb = Bs2[lane];
#pragma unroll
        for (int i = 0; i < 4; i++) {
            int node = n0 + i;
            if (node < N_NODES) {
                float r0 = accx[i] + csum[i] * bb.x;
                float r1 = accy[i] + csum[i] * bb.y;
                *reinterpret_cast<float2*>(out + (size_t)node * IN_CH + 2 * lane) =
                    make_float2(fmaxf(r0, 0.f), fmaxf(r1, 0.f));
            }
        }
    }
}

// =================================================================================
__global__ void __launch_bounds__(NTHR, 5)
k_main(const float* __restrict__ feat, const int* __restrict__ src, const int* __restrict__ dst,
       const float* __restrict__ r, const float* __restrict__ relW, const float* __restrict__ relB,
       const float* c1_lw, const float* c1_lb, const float* c1_aiw, const float* c1_aib,
       const float* c1_ajw, const float* c1_ajb, const float* c1_eww, const float* c1_ewb,
       const float* c2_lw, const float* c2_lb, const float* c2_aiw, const float* c2_aib,
       const float* c2_ajw, const float* c2_ajb, const float* c2_eww, const float* c2_ewb,
       float* __restrict__ out)
{
    __shared__ Smem sm;
    int tid  = threadIdx.x;
    int blk  = blockIdx.x;
    int gtid = blk * NTHR + tid;
    int lane = tid & 31;
    int gwarp = blk * 8 + (tid >> 5);

    // ---------------- P0: init + ewvec ----------------
    for (int i = gtid; i < N_NODES; i += GT) {
        g_deg[i] = 0;
        g_mkey1[i] = 0u; g_ssum1[i] = 0.0f;
        g_mkey2[i] = 0u; g_ssum2[i] = 0.0f;
    }
    if (blk == 0) {
        int t = tid;
        if (t < REL_DIM) {
            float a1 = 0.f, a2 = 0.f;
#pragma unroll
            for (int c = 0; c < IN_CH; c++) {
                float w = relW[c * REL_DIM + t];
                a1 += w * c1_eww[c];
                a2 += w * c2_eww[c];
            }
            g_v1[t] = a1; g_v2[t] = a2;
        } else if (t == 32) {
            float s = 0.f;
            for (int c = 0; c < IN_CH; c++) s += relB[c] * c1_eww[c];
            g_ewc[0] = s + c1_ewb[0];
        } else if (t == 33) {
            float s = 0.f;
            for (int c = 0; c < IN_CH; c++) s += relB[c] * c2_eww[c];
            g_ewc[1] = s + c2_ewb[0];
        }
    }
    gsync(0);

    // ---------------- P1: ew_hist (edges) + transform L1 (nodes) ----------------
    if (tid < REL_DIM) { sm.ew.sv1[tid] = g_v1[tid]; sm.ew.sv2[tid] = g_v2[tid]; }
    if (tid < 2) sm.ew.sc[tid] = g_ewc[tid];
    __syncthreads();
    {
        float c0 = sm.ew.sc[0], c1 = sm.ew.sc[1];
        for (int e = gtid; e < N_EDGES; e += GT) {
            const float4* rp = reinterpret_cast<const float4*>(r + (size_t)e * REL_DIM);
            float a1 = 0.f, a2 = 0.f;
#pragma unroll
            for (int q = 0; q < 8; q++) {
                float4 f = rp[q];
                a1 += f.x * sm.ew.sv1[4*q] + f.y * sm.ew.sv1[4*q+1] + f.z * sm.ew.sv1[4*q+2] + f.w * sm.ew.sv1[4*q+3];
                a2 += f.x * sm.ew.sv2[4*q] + f.y * sm.ew.sv2[4*q+1] + f.z * sm.ew.sv2[4*q+2] + f.w * sm.ew.sv2[4*q+3];
            }
            g_ew1[e] = a1 + c0;
            g_ew2[e] = a2 + c1;
            atomicAdd(&g_deg[dst[e]], 1);
        }
    }
    do_transform(&sm, feat, g_x, c1_lw, c1_lb, c1_aiw, c1_aib, c1_ajw, c1_ajb, gwarp, lane);
    gsync(1);

    // ---------------- P2: scan1 (block-local) + alpha_max L1 ----------------
    if (blk < NCHUNK) {
        int i = blk * 256 + tid;
        int v = (i < N_NODES) ? g_deg[i] : 0;
        int x = v;
#pragma unroll
        for (int off = 1; off < 32; off <<= 1) {
            int y = __shfl_up_sync(0xffffffffu, x, off);
            if (lane >= off) x += y;
        }
        int wid = tid >> 5;
        if (lane == 31) sm.sc.wsum[wid] = x;
        __syncthreads();
        if (wid == 0) {
            int s = (lane < 8) ? sm.sc.wsum[lane] : 0;
#pragma unroll
            for (int off = 1; off < 8; off <<= 1) {
                int y = __shfl_up_sync(0xffffffffu, s, off);
                if (lane >= off) s += y;
            }
            if (lane < 8) sm.sc.wsum[lane] = s;
        }
        __syncthreads();
        int woff = (wid == 0) ? 0 : sm.sc.wsum[wid - 1];
        if (i < N_NODES) g_rowst[i] = woff + x - v;
        if (tid == 255) g_bsum[blk] = woff + x;
        __syncthreads();
    }
    do_alpha_max(src, dst, g_ew1, g_mkey1, gtid);
    gsync(2);

    // ---------------- P3: scan2 (block 0) + exp_sum L1 ----------------
    if (blk == 0) {
        int t = tid, wid = t >> 5;
        int v = (t < NCHUNK) ? g_bsum[t] : 0;
        int x = v;
#pragma unroll
        for (int off = 1; off < 32; off <<= 1) {
            int y = __shfl_up_sync(0xffffffffu, x, off);
            if (lane >= off) x += y;
        }
        if (lane == 31) sm.sc.wsum[wid] = x;
        __syncthreads();
        if (wid == 0) {
            int s = (lane < 8) ? sm.sc.wsum[lane] : 0;
#pragma unroll
            for (int off = 1; off < 8; off <<= 1) {
                int y = __shfl_up_sync(0xffffffffu, s, off);
                if (lane >= off) s += y;
            }
            if (lane < 8) sm.sc.wsum[lane] = s;
        }
        __syncthreads();
        int woff = (wid == 0) ? 0 : sm.sc.wsum[wid - 1];
        if (t < NCHUNK) g_boff[t] = woff + x - v;
        __syncthreads();
    }
    do_exp_sum(src, g_mkey1, g_ssum1, gtid);
    gsync(3);

    // ---------------- P4: scan3 ----------------
    for (int i = gtid; i < N_NODES; i += GT) {
        int v = g_rowst[i] + g_boff[i >> 8];
        g_rowst[i] = v;
        g_curs[i]  = v;
    }
    gsync(4);

    // ---------------- P5: scatter ----------------
    for (int i = gtid; i < N_EDGES; i += GT) {
        int p = atomicAdd(&g_curs[dst[i]], 1);
        g_edge[p] = make_int2(src[i], i);
    }
    gsync(5);

    // ---------------- P6: gather+proj L1 -> g_h, then transform L2 (same warp's
    // nodes: g_h[n] written by this warp; g_x2 is fresh so no cross-block race) ---
    do_gatherproj(&sm, g_x, r, relW, relB, g_ssum1, g_h, gwarp, lane);
    do_transform(&sm, g_h, g_x2, c2_lw, c2_lb, c2_aiw, c2_aib, c2_ajw, c2_ajb, gwarp, lane);
    gsync(6);

    // ---------------- P7: alpha_max L2 ----------------
    do_alpha_max(src, dst, g_ew2, g_mkey2, gtid);
    gsync(7);

    // ---------------- P8: exp_sum L2 ----------------
    do_exp_sum(src, g_mkey2, g_ssum2, gtid);
    gsync(8);

    // ---------------- P9: gather+proj L2 -> out ----------------
    do_gatherproj(&sm, g_x2, r, relW, relB, g_ssum2, out, gwarp, lane);
}

extern "C" void kernel_launch(void* const* d_in, const int* in_sizes, int n_in,
                              void* d_out, int out_size)
{
    const float* feat   = (const float*)d_in[0];
    const int*   eidx   = (const int*)  d_in[1];
    const float* r      = (const float*)d_in[2];
    const float* rel_w  = (const float*)d_in[3];
    const float* rel_b  = (const float*)d_in[4];
    const float* c1_lw  = (const float*)d_in[5];
    const float* c1_lb  = (const float*)d_in[6];
    const float* c1_aiw = (const float*)d_in[7];
    const float* c1_aib = (const float*)d_in[8];
    const float* c1_ajw = (const float*)d_in[9];
    const float* c1_ajb = (const float*)d_in[10];
    const float* c1_eww = (const float*)d_in[11];
    const float* c1_ewb = (const float*)d_in[12];
    const float* c2_lw  = (const float*)d_in[13];
    const float* c2_lb  = (const float*)d_in[14];
    const float* c2_aiw = (const float*)d_in[15];
    const float* c2_aib = (const float*)d_in[16];
    const float* c2_ajw = (const float*)d_in[17];
    const float* c2_ajb = (const float*)d_in[18];
    const float* c2_eww = (const float*)d_in[19];
    const float* c2_ewb = (const float*)d_in[20];
    float* out = (float*)d_out;

    const int* src = eidx;
    const int* dst = eidx + N_EDGES;

    k_main<<<NBLK, NTHR>>>(feat, src, dst, r, rel_w, rel_b,
                           c1_lw, c1_lb, c1_aiw, c1_aib, c1_ajw, c1_ajb, c1_eww, c1_ewb,
                           c2_lw, c2_lb, c2_aiw, c2_aib, c2_ajw, c2_ajb, c2_eww, c2_ewb,
                           out);
}